// round 13
// baseline (speedup 1.0000x reference)
#include <cuda_runtime.h>
#include <cuda_fp16.h>
#include <cstdint>
#include <math.h>

#define HH 56
#define WW 56
#define NB 16
#define C1 64
#define C2 128
#define MU_C 0.1f
#define THR_C 0.01f

// ---------------- device scratch (allocation-free) ----------------
// Winograd-transformed, fragment-ordered fp16 weights:
// fwd : [xi(16)][kbp(2)][cb(16)][ lane(32)*8 + kb2*4 + reg*2 + hp ]
// tcv : [xi(16)][kbp(4)][cb( 8)][ same inner ]
__device__ __half g_Uf[16 * 2 * 16 * 256];   // 131072 halves
__device__ __half g_Ut[16 * 4 * 8 * 256];    // 131072 halves
__device__ float  g_xn[NB * HH * WW * C1];   // x NHWC fp32 (residual aux)
__device__ __half g_xr[NB * HH * WW * C1];   // x NHWC fp16 (conv input)
__device__ float  g_y [NB * HH * WW * C2];   // y fp32 (FISTA aux)
__device__ __half g_yr[NB * HH * WW * C2];   // y fp16 (tconv input)
__device__ float  g_cp[NB * HH * WW * C2];   // c_prev fp32
__device__ __half g_rr[NB * HH * WW * C1];   // residual fp16 (conv input)

__device__ __forceinline__ void mma_f16(float* d, const uint32_t* a,
                                        uint32_t b0, uint32_t b1) {
    asm volatile(
        "mma.sync.aligned.m16n8k16.row.col.f32.f16.f16.f32 "
        "{%0,%1,%2,%3}, {%4,%5,%6,%7}, {%8,%9}, {%0,%1,%2,%3};"
        : "+f"(d[0]), "+f"(d[1]), "+f"(d[2]), "+f"(d[3])
        : "r"(a[0]), "r"(a[1]), "r"(a[2]), "r"(a[3]), "r"(b0), "r"(b1));
}
__device__ __forceinline__ void ldsm_x4(uint32_t* r, uint32_t addr) {
    asm volatile("ldmatrix.sync.aligned.m8n8.x4.shared.b16 {%0,%1,%2,%3}, [%4];"
                 : "=r"(r[0]), "=r"(r[1]), "=r"(r[2]), "=r"(r[3]) : "r"(addr));
}
__device__ __forceinline__ uint32_t smem_u32(const void* p) {
    uint32_t a;
    asm("{ .reg .u64 t; cvta.to.shared.u64 t, %1; cvt.u32.u64 %0, t; }"
        : "=r"(a) : "l"(p));
    return a;
}
__device__ __forceinline__ void cp16(uint32_t dst, const void* src, int sz) {
    asm volatile("cp.async.cg.shared.global [%0], [%1], 16, %2;"
                 :: "r"(dst), "l"(src), "r"(sz));
}
__device__ __forceinline__ void cp_commit_wait() {
    asm volatile("cp.async.commit_group;");
    asm volatile("cp.async.wait_all;" ::: "memory");
}

// ---------------- prep kernels ----------------
__global__ void nchw2nhwc_kernel(const float* __restrict__ src,
                                 float* __restrict__ dfull, __half* __restrict__ rnd) {
    int i = blockIdx.x * 256 + threadIdx.x;
    int total = NB * HH * WW * C1;
    if (i >= total) return;
    int c = i & 63;
    int p = i >> 6;
    int w = p % WW;
    int q = p / WW;
    int h = q % HH;
    int n = q / HH;
    float v = src[((n * C1 + c) * HH + h) * WW + w];
    dfull[i] = v;
    rnd[i] = __float2half_rn(v);
}

// normalize weights + Winograd weight transform U = G g G^T, scatter to frags
__device__ __forceinline__ void wino_u(const float g[3][3], float U[4][4]) {
    float T[4][3];
#pragma unroll
    for (int s = 0; s < 3; s++) {
        T[0][s] = g[0][s];
        T[1][s] = 0.5f * (g[0][s] + g[1][s] + g[2][s]);
        T[2][s] = 0.5f * (g[0][s] - g[1][s] + g[2][s]);
        T[3][s] = g[2][s];
    }
#pragma unroll
    for (int i = 0; i < 4; i++) {
        U[i][0] = T[i][0];
        U[i][1] = 0.5f * (T[i][0] + T[i][1] + T[i][2]);
        U[i][2] = 0.5f * (T[i][0] - T[i][1] + T[i][2]);
        U[i][3] = T[i][2];
    }
}

__global__ void prep_w_kernel(const float* __restrict__ W) {
    const int co = blockIdx.x;      // 0..127
    const int tid = threadIdx.x;
    __shared__ float red[256];
    float s = 0.f;
    for (int i = tid; i < 576; i += 256) {
        float v = W[co * 576 + i];
        s += v * v;
    }
    red[tid] = s;
    __syncthreads();
    for (int off = 128; off > 0; off >>= 1) {
        if (tid < off) red[tid] += red[tid + off];
        __syncthreads();
    }
    const float inv = rsqrtf(red[0] + 1e-12f);
    if (tid < 64) {
        const int ci = tid;
        float g[3][3], gt[3][3];
#pragma unroll
        for (int r = 0; r < 3; r++)
#pragma unroll
            for (int c = 0; c < 3; c++) {
                g[r][c] = W[co * 576 + ci * 9 + r * 3 + c] * inv;
            }
#pragma unroll
        for (int r = 0; r < 3; r++)
#pragma unroll
            for (int c = 0; c < 3; c++) gt[r][c] = g[2 - r][2 - c];

        float Uf[4][4], Ut[4][4];
        wino_u(g, Uf);    // fwd conv: n=co, k=ci
        wino_u(gt, Ut);   // transpose conv: n=ci, k=co, flipped taps
#pragma unroll
        for (int i = 0; i < 4; i++)
#pragma unroll
            for (int j = 0; j < 4; j++) {
                int xi = i * 4 + j;
                {   // fwd scatter: K = ci (64), N = co (128)
                    int kb = ci >> 4, kbp = kb >> 1, kb2 = kb & 1;
                    int cb = co >> 3;
                    int lane = (co & 7) * 4 + ((ci & 7) >> 1);
                    int reg = (ci >> 3) & 1, hp = ci & 1;
                    g_Uf[((xi * 2 + kbp) * 16 + cb) * 256 +
                         lane * 8 + kb2 * 4 + reg * 2 + hp] = __float2half_rn(Uf[i][j]);
                }
                {   // tconv scatter: K = co (128), N = ci (64)
                    int kb = co >> 4, kbp = kb >> 1, kb2 = kb & 1;
                    int cb = ci >> 3;
                    int lane = (ci & 7) * 4 + ((co & 7) >> 1);
                    int reg = (co >> 3) & 1, hp = co & 1;
                    g_Ut[((xi * 4 + kbp) * 8 + cb) * 256 +
                         lane * 8 + kb2 * 4 + reg * 2 + hp] = __float2half_rn(Ut[i][j]);
                }
            }
    }
}

// ---------------- Winograd F(2x2,3x3) conv kernel ----------------
// CTA: one tile-row (ty) = 28 tiles (pad to M=32) x 64 cout.
// Per 64-ci half: stage raw 4x58 px (cp.async), transform to V[16 xi][32][64]
// fp16 in smem, then 16 transform-domain GEMMs with U read via LDG (L1-hot).
// Inverse transform folded into fp32 Y accumulators with +/-1 adds.
// MODE 0: first fwd;  MODE 1: FISTA fwd;  MODE 2: transpose conv + residual
template <int CIN, int COUT, int MODE>
__global__ __launch_bounds__(256, 2)
void wconv(const __half* __restrict__ in, const __half* __restrict__ Uw,
           const float* __restrict__ aux0, const float* __restrict__ aux1,
           float* __restrict__ out0, float* __restrict__ out1,
           __half* __restrict__ out2, float mcoef, int last)
{
    extern __shared__ char smem[];
    constexpr int KHALF = CIN / 64;
    constexpr int NCB   = COUT / 8;
    constexpr int UKBP  = CIN / 32;
    constexpr int RCS   = 144;          // raw col stride (bytes) — bank spread
    constexpr int RRS   = 58 * RCS;     // raw row stride = 8352
    const uint32_t rawu = smem_u32(smem);
    const uint32_t Vb   = rawu + 4 * RRS;        // V base (64 KB)
    char* rawc = smem;

    const int tid  = threadIdx.x;
    const int lane = tid & 31;
    const int w    = tid >> 5;
    const int wm   = w & 1;             // m16 block (tiles)
    const int wn   = w >> 1;            // 16-co block (0..3)

    const int n   = blockIdx.z;
    const int ty  = blockIdx.y;         // tile-row 0..27
    const int co0 = blockIdx.x * 64;
    const int cb0 = co0 >> 3;

    const int tL  = tid >> 3;           // transform: tile 0..31
    const int cpf = tid & 7;

    static const int CA0[4] = {1, 1, 1, 0};
    static const int CA1[4] = {0, 1, -1, -1};

    float2 Yv[2][2][2][2];              // [nb][rh][p][q], co-pair each
#pragma unroll
    for (int a = 0; a < 2; a++)
#pragma unroll
        for (int b = 0; b < 2; b++)
#pragma unroll
            for (int c = 0; c < 2; c++)
#pragma unroll
                for (int d = 0; d < 2; d++) Yv[a][b][c][d] = make_float2(0.f, 0.f);

    for (int kh = 0; kh < KHALF; kh++) {
        // ---- stage raw input: 4 rows x 58 cols x 64 ci (fp16), zero halo
        for (int i = tid; i < 1856; i += 256) {
            int r   = i / 464;
            int rem = i - r * 464;
            int col = rem >> 3;
            int u   = rem & 7;
            int gh = 2 * ty + r - 1;
            int gw = col - 1;
            bool ok = ((unsigned)gh < (unsigned)HH) && ((unsigned)gw < (unsigned)WW);
            const __half* src = in +
                (size_t)((n * HH + (ok ? gh : 0)) * WW + (ok ? gw : 0)) * CIN + kh * 64 + u * 8;
            cp16(rawu + r * RRS + col * RCS + u * 16, src, ok ? 16 : 0);
        }
        cp_commit_wait();
        __syncthreads();   // raw visible; also: prior pass's V readers done

        // ---- input transform: V[xi][tile][ci] fp16 (fp32 math)
        if (tL < 28) {
#pragma unroll
            for (int it = 0; it < 4; it++) {
                int ci = it * 16 + cpf * 2;
                int cg = ci >> 3;
                float2 d[4][4];
#pragma unroll
                for (int r = 0; r < 4; r++)
#pragma unroll
                    for (int j = 0; j < 4; j++) {
                        int s = 2 * tL + j;
                        half2 h2 = *(const half2*)(rawc + r * RRS + s * RCS +
                                                   cg * 16 + (ci & 7) * 2);
                        d[r][j] = __half22float2(h2);
                    }
                float2 t[4][4];
#pragma unroll
                for (int j = 0; j < 4; j++) {
                    t[0][j] = make_float2(d[0][j].x - d[2][j].x, d[0][j].y - d[2][j].y);
                    t[1][j] = make_float2(d[1][j].x + d[2][j].x, d[1][j].y + d[2][j].y);
                    t[2][j] = make_float2(d[2][j].x - d[1][j].x, d[2][j].y - d[1][j].y);
                    t[3][j] = make_float2(d[1][j].x - d[3][j].x, d[1][j].y - d[3][j].y);
                }
#pragma unroll
                for (int i2 = 0; i2 < 4; i2++) {
                    float2 v0 = make_float2(t[i2][0].x - t[i2][2].x, t[i2][0].y - t[i2][2].y);
                    float2 v1 = make_float2(t[i2][1].x + t[i2][2].x, t[i2][1].y + t[i2][2].y);
                    float2 v2 = make_float2(t[i2][2].x - t[i2][1].x, t[i2][2].y - t[i2][1].y);
                    float2 v3 = make_float2(t[i2][1].x - t[i2][3].x, t[i2][1].y - t[i2][3].y);
                    uint32_t base = Vb + tL * 128 + (((uint32_t)(cg ^ (tL & 7))) << 4) +
                                    (ci & 7) * 2;
                    *(half2*)(smem + (base - rawu) + (i2 * 4 + 0) * 4096) = __floats2half2_rn(v0.x, v0.y);
                    *(half2*)(smem + (base - rawu) + (i2 * 4 + 1) * 4096) = __floats2half2_rn(v1.x, v1.y);
                    *(half2*)(smem + (base - rawu) + (i2 * 4 + 2) * 4096) = __floats2half2_rn(v2.x, v2.y);
                    *(half2*)(smem + (base - rawu) + (i2 * 4 + 3) * 4096) = __floats2half2_rn(v3.x, v3.y);
                }
            }
        } else {
            // padding tiles 28..31: zero V
#pragma unroll
            for (int it = 0; it < 4; it++) {
                int ci = it * 16 + cpf * 2;
                int cg = ci >> 3;
                uint32_t base = Vb + tL * 128 + (((uint32_t)(cg ^ (tL & 7))) << 4) +
                                (ci & 7) * 2;
#pragma unroll
                for (int xi = 0; xi < 16; xi++)
                    *(half2*)(smem + (base - rawu) + xi * 4096) = __floats2half2_rn(0.f, 0.f);
            }
        }
        __syncthreads();

        // ---- 16 transform-domain GEMMs (K = 64 per pass)
        const int rb = wm * 16 + (lane & 7) + (lane & 8);
        const int ul = lane >> 4;
#pragma unroll
        for (int xi = 0; xi < 16; xi++) {
            uint32_t a[4][4];
#pragma unroll
            for (int kb = 0; kb < 4; kb++) {
                uint32_t u = kb * 2 + ul;
                ldsm_x4(a[kb], Vb + xi * 4096 + rb * 128 +
                        (((uint32_t)(u ^ (rb & 7))) << 4));
            }
#pragma unroll
            for (int nb = 0; nb < 2; nb++) {
                float mc[4] = {0.f, 0.f, 0.f, 0.f};
                const int cb = cb0 + wn * 2 + nb;
#pragma unroll
                for (int kbpl = 0; kbpl < 2; kbpl++) {
                    const int kbp = kh * 2 + kbpl;
                    uint4 bv = *(const uint4*)(Uw +
                        (size_t)(((xi * UKBP + kbp) * NCB + cb) * 256 + lane * 8));
                    mma_f16(mc, a[kbpl * 2 + 0], bv.x, bv.y);
                    mma_f16(mc, a[kbpl * 2 + 1], bv.z, bv.w);
                }
                // inverse-transform fold: Y[p][q] += cA0/1 coeffs * M
                const int i2 = xi >> 2, j2 = xi & 3;
                float2 Mv0 = make_float2(mc[0], mc[1]);
                float2 Mv1 = make_float2(mc[2], mc[3]);
#pragma unroll
                for (int p = 0; p < 2; p++) {
                    int cp_ = p ? CA1[i2] : CA0[i2];
                    if (cp_ == 0) continue;
#pragma unroll
                    for (int q = 0; q < 2; q++) {
                        int cq = q ? CA1[j2] : CA0[j2];
                        if (cq == 0) continue;
                        float c = (float)(cp_ * cq);
                        Yv[nb][0][p][q].x += c * Mv0.x;
                        Yv[nb][0][p][q].y += c * Mv0.y;
                        Yv[nb][1][p][q].x += c * Mv1.x;
                        Yv[nb][1][p][q].y += c * Mv1.y;
                    }
                }
            }
        }
    }

    // ---- epilogue: fused FISTA ops
#pragma unroll
    for (int nb = 0; nb < 2; nb++) {
#pragma unroll
        for (int rh = 0; rh < 2; rh++) {
            int tile = wm * 16 + (lane >> 2) + rh * 8;
            if (tile >= 28) continue;
            int col = co0 + wn * 16 + nb * 8 + (lane & 3) * 2;
#pragma unroll
            for (int p = 0; p < 2; p++) {
                int h = 2 * ty + p;
#pragma unroll
                for (int q = 0; q < 2; q++) {
                    int wc = 2 * tile + q;
                    size_t o = (size_t)((n * HH + h) * WW + wc) * COUT + col;
                    float v0 = Yv[nb][rh][p][q].x;
                    float v1 = Yv[nb][rh][p][q].y;
                    if (MODE == 0) {
                        float2 r2;
                        r2.x = fmaxf(MU_C * v0 - THR_C, 0.f);
                        r2.y = fmaxf(MU_C * v1 - THR_C, 0.f);
                        *(float2*)(out0 + o) = r2;
                        *(float2*)(out1 + o) = r2;
                        *(half2*)(out2 + o) = __floats2half2_rn(r2.x, r2.y);
                    } else if (MODE == 1) {
                        float2 yv = *(const float2*)(aux0 + o);
                        float cn0 = fmaxf(yv.x + MU_C * v0 - THR_C, 0.f);
                        float cn1 = fmaxf(yv.y + MU_C * v1 - THR_C, 0.f);
                        if (last) {
                            out1[((size_t)(n * C2 + col) * HH + h) * WW + wc] = cn0;
                            out1[((size_t)(n * C2 + col + 1) * HH + h) * WW + wc] = cn1;
                        } else {
                            float2 cpv = *(const float2*)(aux1 + o);
                            float2 c2; c2.x = cn0; c2.y = cn1;
                            *(float2*)(out1 + o) = c2;
                            float2 y2;
                            y2.x = cn0 + mcoef * (cn0 - cpv.x);
                            y2.y = cn1 + mcoef * (cn1 - cpv.y);
                            *(float2*)(out0 + o) = y2;
                            *(half2*)(out2 + o) = __floats2half2_rn(y2.x, y2.y);
                        }
                    } else {
                        float2 xv = *(const float2*)(aux0 + o);
                        *(half2*)(out2 + o) = __floats2half2_rn(xv.x - v0, xv.y - v1);
                    }
                }
            }
        }
    }
}

// ---------------- launcher ----------------
extern "C" void kernel_launch(void* const* d_in, const int* in_sizes, int n_in,
                              void* d_out, int out_size)
{
    const float* x = (const float*)d_in[0];   // [16,64,56,56] NCHW
    const float* W = (const float*)d_in[1];   // [128,64,3,3]
    float* out = (float*)d_out;               // [16,128,56,56] NCHW

    __half *Uf, *Ut, *xr, *yr, *rr;
    float *xn, *y, *cp;
    cudaGetSymbolAddress((void**)&Uf, g_Uf);
    cudaGetSymbolAddress((void**)&Ut, g_Ut);
    cudaGetSymbolAddress((void**)&xn, g_xn);
    cudaGetSymbolAddress((void**)&xr, g_xr);
    cudaGetSymbolAddress((void**)&y,  g_y);
    cudaGetSymbolAddress((void**)&yr, g_yr);
    cudaGetSymbolAddress((void**)&cp, g_cp);
    cudaGetSymbolAddress((void**)&rr, g_rr);

    float mv[5];
    {
        double t = 1.0;
        for (int i = 0; i < 5; i++) {
            double tn = (1.0 + sqrt(1.0 + 4.0 * t * t)) / 2.0;
            mv[i] = (float)((t - 1.0) / tn);
            t = tn;
        }
    }

    const int SMEM = 4 * 8352 + 65536;   // 98944 B -> 2 CTA/SM
    cudaFuncSetAttribute(wconv<C1, C2, 0>, cudaFuncAttributeMaxDynamicSharedMemorySize, SMEM);
    cudaFuncSetAttribute(wconv<C1, C2, 1>, cudaFuncAttributeMaxDynamicSharedMemorySize, SMEM);
    cudaFuncSetAttribute(wconv<C2, C1, 2>, cudaFuncAttributeMaxDynamicSharedMemorySize, SMEM);
    cudaFuncSetAttribute(wconv<C1, C2, 0>, cudaFuncAttributePreferredSharedMemoryCarveout, 100);
    cudaFuncSetAttribute(wconv<C1, C2, 1>, cudaFuncAttributePreferredSharedMemoryCarveout, 100);
    cudaFuncSetAttribute(wconv<C2, C1, 2>, cudaFuncAttributePreferredSharedMemoryCarveout, 100);

    int total = NB * HH * WW * C1;
    nchw2nhwc_kernel<<<(total + 255) / 256, 256>>>(x, xn, xr);
    prep_w_kernel<<<128, 256>>>(W);

    dim3 blk(256, 1, 1);
    dim3 grid_f(C2 / 64, 28, NB);   // (2, 28, 16)
    dim3 grid_t(C1 / 64, 28, NB);   // (1, 28, 16)

    // iteration 0: c = shrink(MU * D^T x); y = c; cp = c
    wconv<C1, C2, 0><<<grid_f, blk, SMEM>>>(xr, Uf, nullptr, nullptr, y, cp, yr, 0.f, 0);

    for (int it = 0; it < 5; it++) {
        // r = x - D y  (transpose conv + residual, fp16 for next conv)
        wconv<C2, C1, 2><<<grid_t, blk, SMEM>>>(yr, Ut, xn, nullptr, nullptr, nullptr, rr, 0.f, 0);
        // c_new = shrink(y + MU * D^T r); momentum
        const int last = (it == 4);
        wconv<C1, C2, 1><<<grid_f, blk, SMEM>>>(rr, Uf, y, cp, y, last ? out : cp, yr,
                                                mv[it], last);
    }
}

// round 14
// speedup vs baseline: 1.3512x; 1.3512x over previous
#include <cuda_runtime.h>
#include <cuda_fp16.h>
#include <cstdint>
#include <math.h>

#define HH 56
#define WW 56
#define NB 16
#define C1 64
#define C2 128
#define MU_C 0.1f
#define THR_C 0.01f

// ---------------- device scratch (allocation-free) ----------------
// fragment-ordered fp16 weights: [kt][co_blk][lane(32)][kblk(2)][reg(2)][half(2)]
__device__ __half g_Wf[2 * 9 * (C2 / 8) * 256];   // 73728 halves
__device__ __half g_Wt[4 * 9 * (C1 / 8) * 256];   // 73728 halves
__device__ float  g_xn[NB * HH * WW * C1];        // x NHWC fp32 (residual aux)
__device__ __half g_xr[NB * HH * WW * C1];        // x NHWC fp16 (conv input)
__device__ float  g_y [NB * HH * WW * C2];        // y fp32 (FISTA aux)
__device__ __half g_yr[NB * HH * WW * C2];        // y fp16 (tconv input)
__device__ float  g_cp[NB * HH * WW * C2];        // c_prev fp32
__device__ __half g_rr[NB * HH * WW * C1];        // residual fp16 (conv input)

__device__ __forceinline__ void mma_f16(float* d, const uint32_t* a,
                                        uint32_t b0, uint32_t b1) {
    asm volatile(
        "mma.sync.aligned.m16n8k16.row.col.f32.f16.f16.f32 "
        "{%0,%1,%2,%3}, {%4,%5,%6,%7}, {%8,%9}, {%0,%1,%2,%3};"
        : "+f"(d[0]), "+f"(d[1]), "+f"(d[2]), "+f"(d[3])
        : "r"(a[0]), "r"(a[1]), "r"(a[2]), "r"(a[3]), "r"(b0), "r"(b1));
}

__device__ __forceinline__ void ldsm_x4(uint32_t* r, uint32_t addr) {
    asm volatile("ldmatrix.sync.aligned.m8n8.x4.shared.b16 {%0,%1,%2,%3}, [%4];"
                 : "=r"(r[0]), "=r"(r[1]), "=r"(r[2]), "=r"(r[3]) : "r"(addr));
}

__device__ __forceinline__ uint32_t smem_u32(const void* p) {
    uint32_t a;
    asm("{ .reg .u64 t; cvta.to.shared.u64 t, %1; cvt.u32.u64 %0, t; }"
        : "=r"(a) : "l"(p));
    return a;
}
__device__ __forceinline__ void cp16(uint32_t dst, const void* src, int sz) {
    asm volatile("cp.async.cg.shared.global [%0], [%1], 16, %2;"
                 :: "r"(dst), "l"(src), "r"(sz));
}
__device__ __forceinline__ void cp_commit_wait() {
    asm volatile("cp.async.commit_group;");
    asm volatile("cp.async.wait_all;" ::: "memory");
}

// ---------------- prep kernels ----------------
__global__ void nchw2nhwc_kernel(const float* __restrict__ src,
                                 float* __restrict__ dfull, __half* __restrict__ rnd) {
    int i = blockIdx.x * 256 + threadIdx.x;
    int total = NB * HH * WW * C1;
    if (i >= total) return;
    int c = i & 63;
    int p = i >> 6;
    int w = p % WW;
    int q = p / WW;
    int h = q % HH;
    int n = q / HH;
    float v = src[((n * C1 + c) * HH + h) * WW + w];
    dfull[i] = v;
    rnd[i] = __float2half_rn(v);
}

__global__ void prep_w_kernel(const float* __restrict__ W) {
    const int co = blockIdx.x;
    const int tid = threadIdx.x;
    __shared__ float red[256];
    float s = 0.f;
    for (int i = tid; i < 576; i += 256) {
        float v = W[co * 576 + i];
        s += v * v;
    }
    red[tid] = s;
    __syncthreads();
    for (int off = 128; off > 0; off >>= 1) {
        if (tid < off) red[tid] += red[tid + off];
        __syncthreads();
    }
    const float inv = rsqrtf(red[0] + 1e-12f);
    for (int i = tid; i < 576; i += 256) {
        int ci = i / 9, tap = i - ci * 9;
        __half v = __float2half_rn(W[co * 576 + i] * inv);
        {   // forward: n = co, k = ci
            int k    = ci & 15;
            int kblk = (ci >> 4) & 1;
            int lane = (co & 7) * 4 + ((k & 7) >> 1);
            int reg  = (k >> 3) & 1;
            int hp   = k & 1;
            int idx  = (((ci >> 5) * 9 + tap) * (C2 / 8) + (co >> 3)) * 256 +
                       lane * 8 + kblk * 4 + reg * 2 + hp;
            g_Wf[idx] = v;
        }
        {   // transpose: n = ci, k = co, flipped tap
            int k    = co & 15;
            int kblk = (co >> 4) & 1;
            int lane = (ci & 7) * 4 + ((k & 7) >> 1);
            int reg  = (k >> 3) & 1;
            int hp   = k & 1;
            int idx  = (((co >> 5) * 9 + (8 - tap)) * (C1 / 8) + (ci >> 3)) * 256 +
                       lane * 8 + kblk * 4 + reg * 2 + hp;
            g_Wt[idx] = v;
        }
    }
}

// ---------------- fp16 mma.sync implicit-GEMM conv (LDSM + LDS.128 B) ------
// PDL: B (weights, upstream-stable) staged BEFORE cudaGridDependencySynchronize;
// A (depends on previous kernel's output) staged after. Implicit at-exit
// completion trigger keeps WAR on rr/yr closed.
// MODE 0: first fwd;  MODE 1: FISTA fwd;  MODE 2: transpose conv + residual
template <int CIN, int COUT, int MODE>
__global__ __launch_bounds__(256, 2)
void mconv(const __half* __restrict__ in, const __half* __restrict__ wgt,
           const float* __restrict__ aux0, const float* __restrict__ aux1,
           float* __restrict__ out0, float* __restrict__ out1,
           __half* __restrict__ out2, float mcoef, int last)
{
    extern __shared__ char smem[];
    constexpr int STR    = CIN * 2;           // bytes per A row
    constexpr int UPR    = CIN / 8;           // 16B units per A row
    constexpr int KH     = CIN / 32;          // 32-ci super-stages
    constexpr bool BRES  = (CIN == 64);       // all B resident?
    constexpr int BUNITS = 9 * 8 * 32;        // B 16B units per kh stage
    char* sBc = smem + 256 * STR;
    const uint32_t sAu = smem_u32(smem);
    const uint32_t sBu = sAu + 256 * STR;

    const int tid  = threadIdx.x;
    const int lane = tid & 31;
    const int w    = tid >> 5;
    const int wm   = w & 3;
    const int wn   = w >> 2;
    const int g    = lane >> 2;
    const int t    = lane & 3;

    const int n   = blockIdx.z;
    const int h0  = blockIdx.y * 2;
    const int co0 = blockIdx.x * 64;
    const int cb0 = co0 >> 3;

    // per-lane LDSM row bases (c = 0 / 1 m-halves)
    const int rb0 = wm * 32 + (lane & 7) + (lane & 8);
    const int rb1 = rb0 + 16;
    const int ulane = lane >> 4;              // +unit for matrices 2,3

    // ---- stage B first (weights: stable many launches upstream -> PDL-safe)
    {
        const int nun = BRES ? KH * BUNITS : BUNITS;
        for (int i = tid; i < nun; i += 256) {
            int chunk = i >> 5;
            int unit  = i & 31;
            int kt  = chunk >> 3;
            int nbl = chunk & 7;
            const __half* src = wgt + (size_t)(kt * (COUT / 8) + cb0 + nbl) * 256 + unit * 8;
            cp16(sBu + chunk * 512 + unit * 16, src, 16);
        }
    }

    // ---- wait for the producing kernel before touching its output
    cudaGridDependencySynchronize();

    // ---- stage A (entire CIN), zero-fill halo
    for (int i = tid; i < 256 * UPR; i += 256) {
        int row = i / UPR;
        int u   = i - row * UPR;
        int rr = row >> 6, cc = row & 63;
        int gh = h0 + rr - 1, gc = cc - 1;
        bool ok = ((unsigned)gh < (unsigned)HH) && ((unsigned)gc < (unsigned)WW);
        const __half* src = in +
            (size_t)((n * HH + (ok ? gh : 0)) * WW + (ok ? gc : 0)) * CIN + u * 8;
        cp16(sAu + row * STR + (((uint32_t)(u ^ (row & 7))) << 4), src, ok ? 16 : 0);
    }
    cp_commit_wait();
    __syncthreads();

    float acc[2][4][4];
#pragma unroll
    for (int c = 0; c < 2; c++)
#pragma unroll
        for (int nb = 0; nb < 4; nb++)
#pragma unroll
            for (int j = 0; j < 4; j++) acc[c][nb][j] = 0.f;

    for (int kh = 0; kh < KH; kh++) {
        if (!BRES && kh > 0) {
            __syncthreads();
            for (int i = tid; i < BUNITS; i += 256) {
                int chunk = i >> 5;
                int unit  = i & 31;
                int tap = chunk >> 3;
                int nbl = chunk & 7;
                const __half* src = wgt +
                    (size_t)((kh * 9 + tap) * (COUT / 8) + cb0 + nbl) * 256 + unit * 8;
                cp16(sBu + chunk * 512 + unit * 16, src, 16);
            }
            cp_commit_wait();
            __syncthreads();
        }

#pragma unroll 3
        for (int tap = 0; tap < 9; tap++) {
            const int ktL = (BRES ? kh * 9 + tap : tap);     // local B block
            const int tapoff = (tap / 3) * 64 + (tap % 3);
            const int r0 = rb0 + tapoff;
            const int r1 = rb1 + tapoff;
            uint32_t a[2][2][4];
#pragma unroll
            for (int kblk = 0; kblk < 2; kblk++) {
                const int u = kh * 4 + kblk * 2 + ulane;
                ldsm_x4(a[0][kblk], sAu + r0 * STR + (((uint32_t)(u ^ (r0 & 7))) << 4));
                ldsm_x4(a[1][kblk], sAu + r1 * STR + (((uint32_t)(u ^ (r1 & 7))) << 4));
            }
#pragma unroll
            for (int nb = 0; nb < 4; nb++) {
                uint4 bv = *(const uint4*)(sBc +
                    (size_t)((ktL * 8 + wn * 4 + nb) * 512) + lane * 16);
                mma_f16(acc[0][nb], a[0][0], bv.x, bv.y);
                mma_f16(acc[1][nb], a[1][0], bv.x, bv.y);
                mma_f16(acc[0][nb], a[0][1], bv.z, bv.w);
                mma_f16(acc[1][nb], a[1][1], bv.z, bv.w);
            }
        }
    }

    // ---- epilogue: fused FISTA ops
#pragma unroll
    for (int c = 0; c < 2; c++) {
#pragma unroll
        for (int half = 0; half < 2; half++) {
            int m = wm * 32 + c * 16 + g + half * 8;
            int rr = m >> 6, cc = m & 63;
            if (cc >= WW) continue;
            int h = h0 + rr;
            size_t pxb = (size_t)((n * HH + h) * WW + cc) * COUT + co0;
#pragma unroll
            for (int nb = 0; nb < 4; nb++) {
                int col = wn * 32 + nb * 8 + 2 * t;
                size_t o = pxb + col;
                float v0 = acc[c][nb][half * 2 + 0];
                float v1 = acc[c][nb][half * 2 + 1];
                if (MODE == 0) {
                    float2 r2;
                    r2.x = fmaxf(MU_C * v0 - THR_C, 0.f);
                    r2.y = fmaxf(MU_C * v1 - THR_C, 0.f);
                    *(float2*)(out0 + o) = r2;                       // y fp32
                    *(float2*)(out1 + o) = r2;                       // c_prev
                    *(half2*)(out2 + o) = __floats2half2_rn(r2.x, r2.y);  // y fp16
                } else if (MODE == 1) {
                    float2 yv = *(const float2*)(aux0 + o);
                    float cn0 = fmaxf(yv.x + MU_C * v0 - THR_C, 0.f);
                    float cn1 = fmaxf(yv.y + MU_C * v1 - THR_C, 0.f);
                    if (last) {
                        out1[((size_t)(n * C2 + co0 + col) * HH + h) * WW + cc] = cn0;
                        out1[((size_t)(n * C2 + co0 + col + 1) * HH + h) * WW + cc] = cn1;
                    } else {
                        float2 cpv = *(const float2*)(aux1 + o);
                        float2 c2; c2.x = cn0; c2.y = cn1;
                        *(float2*)(out1 + o) = c2;                   // c_prev
                        float2 y2;
                        y2.x = cn0 + mcoef * (cn0 - cpv.x);
                        y2.y = cn1 + mcoef * (cn1 - cpv.y);
                        *(float2*)(out0 + o) = y2;                   // y fp32
                        *(half2*)(out2 + o) = __floats2half2_rn(y2.x, y2.y);  // y fp16
                    }
                } else {
                    float2 xv = *(const float2*)(aux0 + o);
                    *(half2*)(out2 + o) = __floats2half2_rn(xv.x - v0, xv.y - v1);  // r fp16
                }
            }
        }
    }
}

// ---------------- PDL launch helper ----------------
template <typename KernT, typename... Args>
static void launch_conv(KernT kern, dim3 grid, dim3 blk, int smem, bool pdl,
                        Args... args)
{
    cudaLaunchConfig_t cfg = {};
    cfg.gridDim = grid;
    cfg.blockDim = blk;
    cfg.dynamicSmemBytes = (size_t)smem;
    cfg.stream = 0;
    cudaLaunchAttribute attr[1];
    if (pdl) {
        attr[0].id = cudaLaunchAttributeProgrammaticStreamSerialization;
        attr[0].val.programmaticStreamSerializationAllowed = 1;
        cfg.attrs = attr;
        cfg.numAttrs = 1;
    }
    cudaLaunchKernelEx(&cfg, kern, args...);
}

// ---------------- launcher ----------------
extern "C" void kernel_launch(void* const* d_in, const int* in_sizes, int n_in,
                              void* d_out, int out_size)
{
    const float* x = (const float*)d_in[0];   // [16,64,56,56] NCHW
    const float* W = (const float*)d_in[1];   // [128,64,3,3]
    float* out = (float*)d_out;               // [16,128,56,56] NCHW

    __half *Wf, *Wt, *xr, *yr, *rr;
    float *xn, *y, *cp;
    cudaGetSymbolAddress((void**)&Wf, g_Wf);
    cudaGetSymbolAddress((void**)&Wt, g_Wt);
    cudaGetSymbolAddress((void**)&xn, g_xn);
    cudaGetSymbolAddress((void**)&xr, g_xr);
    cudaGetSymbolAddress((void**)&y,  g_y);
    cudaGetSymbolAddress((void**)&yr, g_yr);
    cudaGetSymbolAddress((void**)&cp, g_cp);
    cudaGetSymbolAddress((void**)&rr, g_rr);

    float mv[5];
    {
        double t = 1.0;
        for (int i = 0; i < 5; i++) {
            double tn = (1.0 + sqrt(1.0 + 4.0 * t * t)) / 2.0;
            mv[i] = (float)((t - 1.0) / tn);
            t = tn;
        }
    }

    const int SMEM_F = 256 * (C1 * 2) + 2 * 9 * 8 * 512;   // 106496 (2 CTA/SM)
    const int SMEM_T = 256 * (C2 * 2) + 9 * 8 * 512;       // 102400 (2 CTA/SM)
    cudaFuncSetAttribute(mconv<C1, C2, 0>, cudaFuncAttributeMaxDynamicSharedMemorySize, SMEM_F);
    cudaFuncSetAttribute(mconv<C1, C2, 1>, cudaFuncAttributeMaxDynamicSharedMemorySize, SMEM_F);
    cudaFuncSetAttribute(mconv<C2, C1, 2>, cudaFuncAttributeMaxDynamicSharedMemorySize, SMEM_T);
    cudaFuncSetAttribute(mconv<C1, C2, 0>, cudaFuncAttributePreferredSharedMemoryCarveout, 100);
    cudaFuncSetAttribute(mconv<C1, C2, 1>, cudaFuncAttributePreferredSharedMemoryCarveout, 100);
    cudaFuncSetAttribute(mconv<C2, C1, 2>, cudaFuncAttributePreferredSharedMemoryCarveout, 100);

    int total = NB * HH * WW * C1;
    nchw2nhwc_kernel<<<(total + 255) / 256, 256>>>(x, xn, xr);
    prep_w_kernel<<<128, 256>>>(W);

    dim3 blk(256, 1, 1);
    dim3 grid_f(C2 / 64, HH / 2, NB);   // (2, 28, 16)
    dim3 grid_t(C1 / 64, HH / 2, NB);   // (1, 28, 16)

    // iteration 0 (no PDL: its B staging reads prep_w output)
    launch_conv(mconv<C1, C2, 0>, grid_f, blk, SMEM_F, false,
                (const __half*)xr, (const __half*)Wf,
                (const float*)nullptr, (const float*)nullptr,
                y, cp, yr, 0.f, 0);

    for (int it = 0; it < 5; it++) {
        // r = x - D y  (transpose conv + residual, fp16 for next conv)
        launch_conv(mconv<C2, C1, 2>, grid_t, blk, SMEM_T, true,
                    (const __half*)yr, (const __half*)Wt,
                    (const float*)xn, (const float*)nullptr,
                    (float*)nullptr, (float*)nullptr, rr, 0.f, 0);
        // c_new = shrink(y + MU * D^T r); momentum
        const int last = (it == 4);
        launch_conv(mconv<C1, C2, 1>, grid_f, blk, SMEM_F, true,
                    (const __half*)rr, (const __half*)Wf,
                    (const float*)y, (const float*)cp,
                    y, last ? out : cp, yr, mv[it], last);
    }
}

// round 15
// speedup vs baseline: 1.3653x; 1.0104x over previous
#include <cuda_runtime.h>
#include <cuda_fp16.h>
#include <cstdint>
#include <math.h>

#define HH 56
#define WW 56
#define NB 16
#define C1 64
#define C2 128
#define MU_C 0.1f
#define THR_C 0.01f

// ---------------- device scratch (allocation-free) ----------------
__device__ __half g_Wf[2 * 9 * (C2 / 8) * 256];   // fwd weights (frag order)
__device__ __half g_Wt[4 * 9 * (C1 / 8) * 256];   // tconv weights (frag order)
__device__ float  g_xn[NB * HH * WW * C1];
__device__ __half g_xr[NB * HH * WW * C1];
__device__ float  g_y [NB * HH * WW * C2];
__device__ __half g_yr[NB * HH * WW * C2];
__device__ float  g_cp[NB * HH * WW * C2];
__device__ __half g_rr[NB * HH * WW * C1];
__device__ int    g_fy[NB * 28];                  // y/yr tile-row epoch flags
__device__ int    g_fr[NB * 28];                  // rr tile-row epoch flags

__device__ __forceinline__ void mma_f16(float* d, const uint32_t* a,
                                        uint32_t b0, uint32_t b1) {
    asm volatile(
        "mma.sync.aligned.m16n8k16.row.col.f32.f16.f16.f32 "
        "{%0,%1,%2,%3}, {%4,%5,%6,%7}, {%8,%9}, {%0,%1,%2,%3};"
        : "+f"(d[0]), "+f"(d[1]), "+f"(d[2]), "+f"(d[3])
        : "r"(a[0]), "r"(a[1]), "r"(a[2]), "r"(a[3]), "r"(b0), "r"(b1));
}
__device__ __forceinline__ void ldsm_x4(uint32_t* r, uint32_t addr) {
    asm volatile("ldmatrix.sync.aligned.m8n8.x4.shared.b16 {%0,%1,%2,%3}, [%4];"
                 : "=r"(r[0]), "=r"(r[1]), "=r"(r[2]), "=r"(r[3]) : "r"(addr));
}
__device__ __forceinline__ uint32_t smem_u32(const void* p) {
    uint32_t a;
    asm("{ .reg .u64 t; cvta.to.shared.u64 t, %1; cvt.u32.u64 %0, t; }"
        : "=r"(a) : "l"(p));
    return a;
}
__device__ __forceinline__ void cp16(uint32_t dst, const void* src, int sz) {
    asm volatile("cp.async.cg.shared.global [%0], [%1], 16, %2;"
                 :: "r"(dst), "l"(src), "r"(sz));
}
__device__ __forceinline__ void cp_commit_wait() {
    asm volatile("cp.async.commit_group;");
    asm volatile("cp.async.wait_all;" ::: "memory");
}

// ---------------- prep kernels ----------------
__global__ void reset_flags_kernel() {
    int i = threadIdx.x;
    if (i < NB * 28) { g_fy[i] = 0; g_fr[i] = 0; }
}

__global__ void nchw2nhwc_kernel(const float* __restrict__ src,
                                 float* __restrict__ dfull, __half* __restrict__ rnd) {
    int i = blockIdx.x * 256 + threadIdx.x;
    int total = NB * HH * WW * C1;
    if (i >= total) return;
    int c = i & 63;
    int p = i >> 6;
    int w = p % WW;
    int q = p / WW;
    int h = q % HH;
    int n = q / HH;
    float v = src[((n * C1 + c) * HH + h) * WW + w];
    dfull[i] = v;
    rnd[i] = __float2half_rn(v);
}

__global__ void prep_w_kernel(const float* __restrict__ W) {
    const int co = blockIdx.x;
    const int tid = threadIdx.x;
    __shared__ float red[256];
    float s = 0.f;
    for (int i = tid; i < 576; i += 256) {
        float v = W[co * 576 + i];
        s += v * v;
    }
    red[tid] = s;
    __syncthreads();
    for (int off = 128; off > 0; off >>= 1) {
        if (tid < off) red[tid] += red[tid + off];
        __syncthreads();
    }
    const float inv = rsqrtf(red[0] + 1e-12f);
    for (int i = tid; i < 576; i += 256) {
        int ci = i / 9, tap = i - ci * 9;
        __half v = __float2half_rn(W[co * 576 + i] * inv);
        {   // forward: n = co, k = ci
            int k    = ci & 15;
            int kblk = (ci >> 4) & 1;
            int lane = (co & 7) * 4 + ((k & 7) >> 1);
            int reg  = (k >> 3) & 1;
            int hp   = k & 1;
            int idx  = (((ci >> 5) * 9 + tap) * (C2 / 8) + (co >> 3)) * 256 +
                       lane * 8 + kblk * 4 + reg * 2 + hp;
            g_Wf[idx] = v;
        }
        {   // transpose: n = ci, k = co, flipped tap
            int k    = co & 15;
            int kblk = (co >> 4) & 1;
            int lane = (ci & 7) * 4 + ((k & 7) >> 1);
            int reg  = (k >> 3) & 1;
            int hp   = k & 1;
            int idx  = (((co >> 5) * 9 + (8 - tap)) * (C1 / 8) + (ci >> 3)) * 256 +
                       lane * 8 + kblk * 4 + reg * 2 + hp;
            g_Wt[idx] = v;
        }
    }
}

// ---------------- fp16 mma.sync implicit-GEMM conv (pipelined launches) ----
// Tile-level dataflow: early PDL trigger at CTA start; spin on per-(n,ty)
// epoch flags of the producing kernel (3 tile-rows: halo); publish own flag
// after epilogue (fence + atomicAdd).
// MODE 0: first fwd;  MODE 1: FISTA fwd;  MODE 2: transpose conv + residual
template <int CIN, int COUT, int MODE>
__global__ __launch_bounds__(256, 2)
void mconv(const __half* __restrict__ in, const __half* __restrict__ wgt,
           const float* __restrict__ aux0, const float* __restrict__ aux1,
           float* __restrict__ out0, float* __restrict__ out1,
           __half* __restrict__ out2, float mcoef, int last,
           int* wflag, int wtarget, int* pflag)
{
    extern __shared__ char smem[];
    constexpr int STR    = CIN * 2;           // bytes per A row
    constexpr int UPR    = CIN / 8;           // 16B units per A row
    constexpr int KH     = CIN / 32;          // 32-ci super-stages
    constexpr bool BRES  = (CIN == 64);       // all B resident?
    constexpr int BUNITS = 9 * 8 * 32;        // B 16B units per kh stage
    char* sBc = smem + 256 * STR;
    const uint32_t sAu = smem_u32(smem);
    const uint32_t sBu = sAu + 256 * STR;

    const int tid  = threadIdx.x;
    const int lane = tid & 31;
    const int w    = tid >> 5;
    const int wm   = w & 3;
    const int wn   = w >> 2;
    const int g    = lane >> 2;
    const int t    = lane & 3;

    const int n   = blockIdx.z;
    const int ty  = blockIdx.y;
    const int h0  = ty * 2;
    const int co0 = blockIdx.x * 64;
    const int cb0 = co0 >> 3;

    const int rb0 = wm * 32 + (lane & 7) + (lane & 8);
    const int rb1 = rb0 + 16;
    const int ulane = lane >> 4;

    // allow the next kernel in the stream to start launching immediately
    if (tid == 0) cudaTriggerProgrammaticLaunchCompletion();

    // ---- stage B first (weights: stable many launches upstream)
    {
        const int nun = BRES ? KH * BUNITS : BUNITS;
        for (int i = tid; i < nun; i += 256) {
            int chunk = i >> 5;
            int unit  = i & 31;
            int kt  = chunk >> 3;
            int nbl = chunk & 7;
            const __half* src = wgt + (size_t)(kt * (COUT / 8) + cb0 + nbl) * 256 + unit * 8;
            cp16(sBu + chunk * 512 + unit * 16, src, 16);
        }
    }

    // ---- wait for producer tiles (ty-1, ty, ty+1) of previous kernel
    if (MODE != 0) {
        if (tid < 3) {
            int tyq = ty + tid - 1;
            if (tyq < 0) tyq = 0;
            if (tyq > 27) tyq = 27;
            while (atomicAdd(&wflag[n * 28 + tyq], 0) < wtarget) { }
        }
        __syncthreads();
        __threadfence();
    }

    // ---- stage A (entire CIN), zero-fill halo
    for (int i = tid; i < 256 * UPR; i += 256) {
        int row = i / UPR;
        int u   = i - row * UPR;
        int rr = row >> 6, cc = row & 63;
        int gh = h0 + rr - 1, gc = cc - 1;
        bool ok = ((unsigned)gh < (unsigned)HH) && ((unsigned)gc < (unsigned)WW);
        const __half* src = in +
            (size_t)((n * HH + (ok ? gh : 0)) * WW + (ok ? gc : 0)) * CIN + u * 8;
        cp16(sAu + row * STR + (((uint32_t)(u ^ (row & 7))) << 4), src, ok ? 16 : 0);
    }
    cp_commit_wait();
    __syncthreads();

    float acc[2][4][4];
#pragma unroll
    for (int c = 0; c < 2; c++)
#pragma unroll
        for (int nb = 0; nb < 4; nb++)
#pragma unroll
            for (int j = 0; j < 4; j++) acc[c][nb][j] = 0.f;

    for (int kh = 0; kh < KH; kh++) {
        if (!BRES && kh > 0) {
            __syncthreads();
            for (int i = tid; i < BUNITS; i += 256) {
                int chunk = i >> 5;
                int unit  = i & 31;
                int tap = chunk >> 3;
                int nbl = chunk & 7;
                const __half* src = wgt +
                    (size_t)((kh * 9 + tap) * (COUT / 8) + cb0 + nbl) * 256 + unit * 8;
                cp16(sBu + chunk * 512 + unit * 16, src, 16);
            }
            cp_commit_wait();
            __syncthreads();
        }

#pragma unroll 3
        for (int tap = 0; tap < 9; tap++) {
            const int ktL = (BRES ? kh * 9 + tap : tap);
            const int tapoff = (tap / 3) * 64 + (tap % 3);
            const int r0 = rb0 + tapoff;
            const int r1 = rb1 + tapoff;
            uint32_t a[2][2][4];
#pragma unroll
            for (int kblk = 0; kblk < 2; kblk++) {
                const int u = kh * 4 + kblk * 2 + ulane;
                ldsm_x4(a[0][kblk], sAu + r0 * STR + (((uint32_t)(u ^ (r0 & 7))) << 4));
                ldsm_x4(a[1][kblk], sAu + r1 * STR + (((uint32_t)(u ^ (r1 & 7))) << 4));
            }
#pragma unroll
            for (int nb = 0; nb < 4; nb++) {
                uint4 bv = *(const uint4*)(sBc +
                    (size_t)((ktL * 8 + wn * 4 + nb) * 512) + lane * 16);
                mma_f16(acc[0][nb], a[0][0], bv.x, bv.y);
                mma_f16(acc[1][nb], a[1][0], bv.x, bv.y);
                mma_f16(acc[0][nb], a[0][1], bv.z, bv.w);
                mma_f16(acc[1][nb], a[1][1], bv.z, bv.w);
            }
        }
    }

    // ---- epilogue: fused FISTA ops
#pragma unroll
    for (int c = 0; c < 2; c++) {
#pragma unroll
        for (int half = 0; half < 2; half++) {
            int m = wm * 32 + c * 16 + g + half * 8;
            int rr = m >> 6, cc = m & 63;
            if (cc >= WW) continue;
            int h = h0 + rr;
            size_t pxb = (size_t)((n * HH + h) * WW + cc) * COUT + co0;
#pragma unroll
            for (int nb = 0; nb < 4; nb++) {
                int col = wn * 32 + nb * 8 + 2 * t;
                size_t o = pxb + col;
                float v0 = acc[c][nb][half * 2 + 0];
                float v1 = acc[c][nb][half * 2 + 1];
                if (MODE == 0) {
                    float2 r2;
                    r2.x = fmaxf(MU_C * v0 - THR_C, 0.f);
                    r2.y = fmaxf(MU_C * v1 - THR_C, 0.f);
                    *(float2*)(out0 + o) = r2;
                    *(float2*)(out1 + o) = r2;
                    *(half2*)(out2 + o) = __floats2half2_rn(r2.x, r2.y);
                } else if (MODE == 1) {
                    float2 yv = *(const float2*)(aux0 + o);
                    float cn0 = fmaxf(yv.x + MU_C * v0 - THR_C, 0.f);
                    float cn1 = fmaxf(yv.y + MU_C * v1 - THR_C, 0.f);
                    if (last) {
                        out1[((size_t)(n * C2 + co0 + col) * HH + h) * WW + cc] = cn0;
                        out1[((size_t)(n * C2 + co0 + col + 1) * HH + h) * WW + cc] = cn1;
                    } else {
                        float2 cpv = *(const float2*)(aux1 + o);
                        float2 c2; c2.x = cn0; c2.y = cn1;
                        *(float2*)(out1 + o) = c2;
                        float2 y2;
                        y2.x = cn0 + mcoef * (cn0 - cpv.x);
                        y2.y = cn1 + mcoef * (cn1 - cpv.y);
                        *(float2*)(out0 + o) = y2;
                        *(half2*)(out2 + o) = __floats2half2_rn(y2.x, y2.y);
                    }
                } else {
                    float2 xv = *(const float2*)(aux0 + o);
                    *(half2*)(out2 + o) = __floats2half2_rn(xv.x - v0, xv.y - v1);
                }
            }
        }
    }

    // ---- publish tile flag (release)
    if (pflag) {
        __threadfence();
        __syncthreads();
        if (tid == 0) atomicAdd(&pflag[n * 28 + ty], 1);
    }
}

// ---------------- PDL launch helper ----------------
template <typename KernT, typename... Args>
static void launch_conv(KernT kern, dim3 grid, dim3 blk, int smem, bool pdl,
                        Args... args)
{
    cudaLaunchConfig_t cfg = {};
    cfg.gridDim = grid;
    cfg.blockDim = blk;
    cfg.dynamicSmemBytes = (size_t)smem;
    cfg.stream = 0;
    cudaLaunchAttribute attr[1];
    if (pdl) {
        attr[0].id = cudaLaunchAttributeProgrammaticStreamSerialization;
        attr[0].val.programmaticStreamSerializationAllowed = 1;
        cfg.attrs = attr;
        cfg.numAttrs = 1;
    }
    cudaLaunchKernelEx(&cfg, kern, args...);
}

// ---------------- launcher ----------------
extern "C" void kernel_launch(void* const* d_in, const int* in_sizes, int n_in,
                              void* d_out, int out_size)
{
    const float* x = (const float*)d_in[0];   // [16,64,56,56] NCHW
    const float* W = (const float*)d_in[1];   // [128,64,3,3]
    float* out = (float*)d_out;               // [16,128,56,56] NCHW

    __half *Wf, *Wt, *xr, *yr, *rr;
    float *xn, *y, *cp;
    int *fy, *fr;
    cudaGetSymbolAddress((void**)&Wf, g_Wf);
    cudaGetSymbolAddress((void**)&Wt, g_Wt);
    cudaGetSymbolAddress((void**)&xn, g_xn);
    cudaGetSymbolAddress((void**)&xr, g_xr);
    cudaGetSymbolAddress((void**)&y,  g_y);
    cudaGetSymbolAddress((void**)&yr, g_yr);
    cudaGetSymbolAddress((void**)&cp, g_cp);
    cudaGetSymbolAddress((void**)&rr, g_rr);
    cudaGetSymbolAddress((void**)&fy, g_fy);
    cudaGetSymbolAddress((void**)&fr, g_fr);

    float mv[5];
    {
        double t = 1.0;
        for (int i = 0; i < 5; i++) {
            double tn = (1.0 + sqrt(1.0 + 4.0 * t * t)) / 2.0;
            mv[i] = (float)((t - 1.0) / tn);
            t = tn;
        }
    }

    const int SMEM_F = 256 * (C1 * 2) + 2 * 9 * 8 * 512;   // 106496 (2 CTA/SM)
    const int SMEM_T = 256 * (C2 * 2) + 9 * 8 * 512;       // 102400 (2 CTA/SM)
    cudaFuncSetAttribute(mconv<C1, C2, 0>, cudaFuncAttributeMaxDynamicSharedMemorySize, SMEM_F);
    cudaFuncSetAttribute(mconv<C1, C2, 1>, cudaFuncAttributeMaxDynamicSharedMemorySize, SMEM_F);
    cudaFuncSetAttribute(mconv<C2, C1, 2>, cudaFuncAttributeMaxDynamicSharedMemorySize, SMEM_T);
    cudaFuncSetAttribute(mconv<C1, C2, 0>, cudaFuncAttributePreferredSharedMemoryCarveout, 100);
    cudaFuncSetAttribute(mconv<C1, C2, 1>, cudaFuncAttributePreferredSharedMemoryCarveout, 100);
    cudaFuncSetAttribute(mconv<C2, C1, 2>, cudaFuncAttributePreferredSharedMemoryCarveout, 100);

    reset_flags_kernel<<<1, 512>>>();
    int total = NB * HH * WW * C1;
    nchw2nhwc_kernel<<<(total + 255) / 256, 256>>>(x, xn, xr);
    prep_w_kernel<<<128, 256>>>(W);

    dim3 blk(256, 1, 1);
    dim3 grid_f(C2 / 64, HH / 2, NB);   // (2, 28, 16)
    dim3 grid_t(C1 / 64, HH / 2, NB);   // (1, 28, 16)

    // iteration 0 (non-PDL: B staging reads prep_w output); publishes fy (->2)
    launch_conv(mconv<C1, C2, 0>, grid_f, blk, SMEM_F, false,
                (const __half*)xr, (const __half*)Wf,
                (const float*)nullptr, (const float*)nullptr,
                y, cp, yr, 0.f, 0,
                (int*)nullptr, 0, fy);

    for (int it = 1; it <= 5; it++) {
        // tconv epoch it: waits fy >= 2*it, publishes fr (-> it)
        launch_conv(mconv<C2, C1, 2>, grid_t, blk, SMEM_T, true,
                    (const __half*)yr, (const __half*)Wt,
                    (const float*)xn, (const float*)nullptr,
                    (float*)nullptr, (float*)nullptr, rr, 0.f, 0,
                    fy, 2 * it, fr);
        // fwd epoch it: waits fr >= it, publishes fy (-> 2*(it+1)); last: no flag
        const int last = (it == 5);
        launch_conv(mconv<C1, C2, 1>, grid_f, blk, SMEM_F, true,
                    (const __half*)rr, (const __half*)Wf,
                    (const float*)y, (const float*)cp,
                    y, last ? out : cp, yr, mv[it - 1], last,
                    fr, it, last ? (int*)nullptr : fy);
    }
}